// round 15
// baseline (speedup 1.0000x reference)
#include <cuda_runtime.h>
#include <cuda_bf16.h>
#include <math.h>
#include <stdint.h>

#define N_ENT   50000
#define NREL    200
#define DIM     128
#define NB      4
#define E_EDGES 200000
#define S_SAMP  20000
#define KTOT    640   /* GEMM K: 512 (Z) + 128 (X) */
#define CAP     128   /* slot capacity per dst */
#define CH      40    /* smem chunk row stride (halfs): 32 + pad */
#define BM      64    /* GEMM m-tile rows */
#define MT64    782   /* ceil(50000/64) */
#define PGRID   296   /* persistent grid: 148 SMs x 2 CTAs */

// ---------------- scratch (device globals; no runtime allocation) ----------
__device__ __nv_bfloat16 g_Ab[(size_t)N_ENT * KTOT];  // A hi = [Zmean | X]
__device__ __nv_bfloat16 g_As[(size_t)N_ENT * KTOT];  // A lo
__device__ __nv_bfloat16 g_Wb[2][DIM * KTOT];         // W^T hi, per layer
__device__ __nv_bfloat16 g_Ws[2][DIM * KTOT];         // W^T lo, per layer
__device__ float g_XF[(size_t)N_ENT * DIM];           // current x (fp32)
__device__ int   g_deg[N_ENT];
__device__ int   g_ssrc[(size_t)N_ENT * CAP];         // slot payload: src node
__device__ int2  g_mt[(size_t)N_ENT * CAP];           // slot payload: (etype, norm)
__device__ float g_relT[NREL * DIM];
__device__ float g_relC[NREL * DIM];

// ---------------- PTX helpers ------------------------------------------------
__device__ __forceinline__ uint32_t smem_u32(const void* p) {
    uint32_t a;
    asm("{ .reg .u64 t; cvta.to.shared.u64 t, %1; cvt.u32.u64 %0, t; }"
        : "=r"(a) : "l"(p));
    return a;
}
__device__ __forceinline__ void cp16(uint32_t dst_s, const void* src) {
    asm volatile("cp.async.cg.shared.global [%0], [%1], 16;"
                 :: "r"(dst_s), "l"(src));
}
#define CP_COMMIT() asm volatile("cp.async.commit_group;" ::: "memory")
#define CP_WAIT1()  asm volatile("cp.async.wait_group 1;" ::: "memory")
#define CP_WAIT0()  asm volatile("cp.async.wait_group 0;" ::: "memory")

__device__ __forceinline__ void mma_bf16(float* d, const uint32_t* a,
                                         uint32_t b0, uint32_t b1) {
    asm volatile(
        "mma.sync.aligned.m16n8k16.row.col.f32.bf16.bf16.f32 "
        "{%0,%1,%2,%3}, {%4,%5,%6,%7}, {%8,%9}, {%0,%1,%2,%3};"
        : "+f"(d[0]), "+f"(d[1]), "+f"(d[2]), "+f"(d[3])
        : "r"(a[0]), "r"(a[1]), "r"(a[2]), "r"(a[3]), "r"(b0), "r"(b1));
}
#define LDSM4(r0, r1, r2, r3, addr) \
    asm volatile("ldmatrix.sync.aligned.m8n8.x4.shared.b16 {%0,%1,%2,%3}, [%4];" \
                 : "=r"(r0), "=r"(r1), "=r"(r2), "=r"(r3) : "r"(addr))

__device__ __forceinline__ uint32_t pack_bf2(float lo, float hi) {
    __nv_bfloat16 a = __float2bfloat16_rn(lo);
    __nv_bfloat16 b = __float2bfloat16_rn(hi);
    return (uint32_t)__bfloat16_as_ushort(a) |
           ((uint32_t)__bfloat16_as_ushort(b) << 16);
}
__device__ __forceinline__ void split2(float v, float& hi, float& lo) {
    __nv_bfloat16 h = __float2bfloat16_rn(v);
    hi = __bfloat162float(h);
    lo = v - hi;
}
__device__ __forceinline__ float sigmoidf(float x) {
    return 1.0f / (1.0f + expf(-x));
}

// ---------------- setup kernels ----------------------------------------------
__global__ void zero_deg_k() {
    int i = blockIdx.x * blockDim.x + threadIdx.x;
    if (i < N_ENT) g_deg[i] = 0;
}

// pack full edge payload into slot tables
__global__ void fill_k(const int* __restrict__ dst, const int* __restrict__ src,
                       const int* __restrict__ etype, const float* __restrict__ enorm) {
    int e = blockIdx.x * blockDim.x + threadIdx.x;
    if (e >= E_EDGES) return;
    int d = dst[e];
    int pos = atomicAdd(&g_deg[d], 1);
    if (pos < CAP) {
        size_t off = (size_t)d * CAP + pos;
        g_ssrc[off] = src[e];
        g_mt[off] = make_int2(etype[e], __float_as_int(enorm[e]));
    }
}

// W^T[j][c]: c<512 -> basis[b=c/128][i=c%128][j] ; c>=512 -> root[c-512][j]
__global__ void build_w_split(const float* __restrict__ basis,
                              const float* __restrict__ root, int layer) {
    int idx = blockIdx.x * blockDim.x + threadIdx.x;  // DIM*KTOT
    if (idx >= DIM * KTOT) return;
    int j = idx / KTOT, c = idx % KTOT;
    float w;
    if (c < 512) w = basis[(size_t)c * DIM + j];
    else         w = root[(size_t)(c - 512) * DIM + j];
    float hi, lo;
    split2(w, hi, lo);
    g_Wb[layer][idx] = __float2bfloat16_rn(hi);
    g_Ws[layer][idx] = __float2bfloat16_rn(lo);
}

// X0 = entity_context_tab[entity] -> XF fp32 + bf16 splits (A cols 512..639)
__global__ void gather_x0(const int* __restrict__ entity,
                          const float* __restrict__ ectx) {
    int idx = blockIdx.x * blockDim.x + threadIdx.x;  // N_ENT*32
    if (idx >= N_ENT * 32) return;
    int n = idx >> 5, q = idx & 31;
    float4 x = ((const float4*)(ectx + (size_t)entity[n] * DIM))[q];
    ((float4*)(g_XF + (size_t)n * DIM))[q] = x;
    float h0, l0, h1, l1, h2, l2, h3, l3;
    split2(x.x, h0, l0); split2(x.y, h1, l1);
    split2(x.z, h2, l2); split2(x.w, h3, l3);
    size_t off = (size_t)n * KTOT + 512 + q * 4;
    *(uint2*)(g_Ab + off) = make_uint2(pack_bf2(h0, h1), pack_bf2(h2, h3));
    *(uint2*)(g_As + off) = make_uint2(pack_bf2(l0, l1), pack_bf2(l2, l3));
}

// ---------------- edge gather -------------------------------------------------
__device__ __forceinline__ void accum16(float* z, float4 a, float nrm, float4 x) {
    float c;
    c = a.x * nrm; z[0]  += c * x.x; z[1]  += c * x.y; z[2]  += c * x.z; z[3]  += c * x.w;
    c = a.y * nrm; z[4]  += c * x.x; z[5]  += c * x.y; z[6]  += c * x.z; z[7]  += c * x.w;
    c = a.z * nrm; z[8]  += c * x.x; z[9]  += c * x.y; z[10] += c * x.z; z[11] += c * x.w;
    c = a.w * nrm; z[12] += c * x.x; z[13] += c * x.y; z[14] += c * x.z; z[15] += c * x.w;
}

// warp per dst; slot payload is pre-packed (no per-edge indirection)
__global__ void edge_gather(const float* __restrict__ att) {
    int d = (blockIdx.x * blockDim.x + threadIdx.x) >> 5;
    int lane = threadIdx.x & 31;
    if (d >= N_ENT) return;
    int degf = g_deg[d];
    int deg = degf < CAP ? degf : CAP;
    const int* ssrc = g_ssrc + (size_t)d * CAP;
    const int2* mt = g_mt + (size_t)d * CAP;

    float z[16];
#pragma unroll
    for (int i = 0; i < 16; i++) z[i] = 0.0f;

    int i = 0;
    for (; i + 4 <= deg; i += 4) {
        int4 ss = *(const int4*)(ssrc + i);
        int4 m01 = *(const int4*)(mt + i);
        int4 m23 = *(const int4*)(mt + i + 2);
        float4 a0 = *(const float4*)(att + (size_t)m01.x * 4);
        float4 a1 = *(const float4*)(att + (size_t)m01.z * 4);
        float4 a2 = *(const float4*)(att + (size_t)m23.x * 4);
        float4 a3 = *(const float4*)(att + (size_t)m23.z * 4);
        float4 x0 = ((const float4*)(g_XF + (size_t)ss.x * DIM))[lane];
        float4 x1 = ((const float4*)(g_XF + (size_t)ss.y * DIM))[lane];
        float4 x2 = ((const float4*)(g_XF + (size_t)ss.z * DIM))[lane];
        float4 x3 = ((const float4*)(g_XF + (size_t)ss.w * DIM))[lane];
        accum16(z, a0, __int_as_float(m01.y), x0);
        accum16(z, a1, __int_as_float(m01.w), x1);
        accum16(z, a2, __int_as_float(m23.y), x2);
        accum16(z, a3, __int_as_float(m23.w), x3);
    }
    for (; i < deg; i++) {
        int s = ssrc[i];
        int2 m = mt[i];
        float4 a = *(const float4*)(att + (size_t)m.x * 4);
        float4 x = ((const float4*)(g_XF + (size_t)s * DIM))[lane];
        accum16(z, a, __int_as_float(m.y), x);
    }

    float inv = 1.0f / (float)(degf > 1 ? degf : 1);
#pragma unroll
    for (int b = 0; b < 4; b++) {
        float h0, l0, h1, l1, h2, l2, h3, l3;
        split2(z[b * 4 + 0] * inv, h0, l0);
        split2(z[b * 4 + 1] * inv, h1, l1);
        split2(z[b * 4 + 2] * inv, h2, l2);
        split2(z[b * 4 + 3] * inv, h3, l3);
        size_t off = (size_t)d * KTOT + b * 128 + lane * 4;
        *(uint2*)(g_Ab + off) = make_uint2(pack_bf2(h0, h1), pack_bf2(h2, h3));
        *(uint2*)(g_As + off) = make_uint2(pack_bf2(l0, l1), pack_bf2(l2, l3));
    }
}

// ---------------- 3xBF16 persistent GEMM: relu(A[M,640] @ W^T + bias) --------
// BM=64 tiles, grid PGRID persistent; warp tile 32x32 (2m x 4n warps).
#define ABUF_H (2 * BM * CH)          /* 5120 halfs = 10240 B per buffer */
#define WBUF_H (2 * 128 * CH)         /* 10240 halfs = 20480 B per buffer */
#define SMEM_SZ ((2 * ABUF_H + 2 * WBUF_H) * 2)   /* 61440 B */

__device__ __forceinline__ void load_a_chunk(uint32_t sbase, int row0, int maxrow,
                                             int kc, int tid) {
    int r = tid >> 2, q = tid & 3;       // 64 rows x 4 eighths
    int gr = row0 + r;
    if (gr >= maxrow) gr = 0;
    const __nv_bfloat16* ph = g_Ab + (size_t)gr * KTOT + kc * 32 + q * 8;
    const __nv_bfloat16* pl = g_As + (size_t)gr * KTOT + kc * 32 + q * 8;
    uint32_t dh = sbase + (uint32_t)(r * CH + q * 8) * 2;
    cp16(dh, ph);
    cp16(dh + (uint32_t)(BM * CH) * 2, pl);
}

__device__ __forceinline__ void load_w_chunk(uint32_t sbase, const __nv_bfloat16* hi,
                                             const __nv_bfloat16* lo, int kc, int tid) {
    int r = tid >> 1, h = tid & 1;       // 128 rows x 2 halves
    const __nv_bfloat16* ph = hi + (size_t)r * KTOT + kc * 32 + h * 16;
    const __nv_bfloat16* pl = lo + (size_t)r * KTOT + kc * 32 + h * 16;
    uint32_t dh = sbase + (uint32_t)(r * CH + h * 16) * 2;
    uint32_t dl = dh + (uint32_t)(128 * CH) * 2;
    cp16(dh, ph);       cp16(dh + 16, ph + 8);
    cp16(dl, pl);       cp16(dl + 16, pl + 8);
}

__global__ void __launch_bounds__(256, 2)
gemm_mma(const float* __restrict__ bias, int write_split, int layer, int M) {
    extern __shared__ char smraw[];
    uint32_t sA_u = smem_u32(smraw);
    uint32_t sW_u = sA_u + (uint32_t)(2 * ABUF_H) * 2;
    const __nv_bfloat16* Wb = g_Wb[layer];
    const __nv_bfloat16* Ws = g_Ws[layer];

    int tid = threadIdx.x;
    int wid = tid >> 5;
    int lane = tid & 31;
    int wm = (wid & 1) * 32;          // 2 m-warp groups
    int wn = (wid >> 1) * 32;         // 4 n-warp groups
    int f_r = lane & 15;
    int f_c = (lane >> 4) << 3;

    for (int mt = blockIdx.x; mt < MT64; mt += gridDim.x) {
        int m0 = mt * BM;

        float acc[2][4][4];
#pragma unroll
        for (int i = 0; i < 2; i++)
#pragma unroll
            for (int j = 0; j < 4; j++)
#pragma unroll
                for (int q = 0; q < 4; q++) acc[i][j][q] = 0.0f;

        load_a_chunk(sA_u, m0, M, 0, tid);
        load_w_chunk(sW_u, Wb, Ws, 0, tid);
        CP_COMMIT();

        int buf = 0;
        for (int kc = 0; kc < 20; kc++) {
            if (kc + 1 < 20) {
                load_a_chunk(sA_u + (uint32_t)((buf ^ 1) * ABUF_H) * 2, m0, M, kc + 1, tid);
                load_w_chunk(sW_u + (uint32_t)((buf ^ 1) * WBUF_H) * 2, Wb, Ws, kc + 1, tid);
                CP_COMMIT();
                CP_WAIT1();
            } else {
                CP_WAIT0();
            }
            __syncthreads();

            uint32_t sa = sA_u + (uint32_t)(buf * ABUF_H) * 2;
            uint32_t sw = sW_u + (uint32_t)(buf * WBUF_H) * 2;
#pragma unroll
            for (int k16 = 0; k16 < 2; k16++) {
                int ak = k16 * 16 + f_c;
                uint32_t ab[2][4], av[2][4];
#pragma unroll
                for (int ma = 0; ma < 2; ma++) {
                    uint32_t ad = sa + (uint32_t)((wm + ma * 16 + f_r) * CH + ak) * 2;
                    LDSM4(ab[ma][0], ab[ma][1], ab[ma][2], ab[ma][3], ad);
                    LDSM4(av[ma][0], av[ma][1], av[ma][2], av[ma][3],
                          ad + (uint32_t)(BM * CH) * 2);
                }
                uint32_t wb[2][4], ws[2][4];
#pragma unroll
                for (int g = 0; g < 2; g++) {
                    uint32_t off = (uint32_t)((wn + g * 16 + f_r) * CH + ak) * 2;
                    LDSM4(wb[g][0], wb[g][1], wb[g][2], wb[g][3], sw + off);
                    LDSM4(ws[g][0], ws[g][1], ws[g][2], ws[g][3],
                          sw + (uint32_t)(128 * CH) * 2 + off);
                }
#pragma unroll
                for (int ma = 0; ma < 2; ma++)
#pragma unroll
                    for (int g = 0; g < 2; g++)
#pragma unroll
                        for (int oc = 0; oc < 2; oc++) {
                            int na = g * 2 + oc;
                            mma_bf16(acc[ma][na], ab[ma], wb[g][oc], wb[g][oc + 2]);
                            mma_bf16(acc[ma][na], ab[ma], ws[g][oc], ws[g][oc + 2]);
                            mma_bf16(acc[ma][na], av[ma], wb[g][oc], wb[g][oc + 2]);
                        }
            }
            __syncthreads();
            buf ^= 1;
        }

        // ---- epilogue: +bias, relu -> XF (+ bf16 splits for next layer) ----
        int lr = lane >> 2, lc = lane & 3;
#pragma unroll
        for (int ma = 0; ma < 2; ma++) {
#pragma unroll
            for (int rr = 0; rr < 2; rr++) {
                int gr = m0 + wm + ma * 16 + rr * 8 + lr;
                if (gr >= M) continue;
#pragma unroll
                for (int na = 0; na < 4; na++) {
                    int gc = wn + na * 8 + lc * 2;
                    float v0 = acc[ma][na][rr * 2 + 0] + bias[gc];
                    float v1 = acc[ma][na][rr * 2 + 1] + bias[gc + 1];
                    v0 = v0 > 0.0f ? v0 : 0.0f;
                    v1 = v1 > 0.0f ? v1 : 0.0f;
                    *(float2*)(g_XF + (size_t)gr * DIM + gc) = make_float2(v0, v1);
                    if (write_split) {
                        float h0, l0, h1, l1;
                        split2(v0, h0, l0);
                        split2(v1, h1, l1);
                        size_t off = (size_t)gr * KTOT + 512 + gc;
                        *(uint32_t*)(g_Ab + off) = pack_bf2(h0, h1);
                        *(uint32_t*)(g_As + off) = pack_bf2(l0, l1);
                    }
                }
            }
        }
        __syncthreads();   // protect smem before next tile's loads
    }
}

// ---------------- relation GCN (tiny) ----------------------------------------
__global__ void rel_gemm1(const float* __restrict__ DAD, const float* __restrict__ RC) {
    int idx = blockIdx.x * blockDim.x + threadIdx.x;
    if (idx >= NREL * DIM) return;
    int i = idx >> 7, j = idx & 127;
    float s = 0.0f;
    for (int k = 0; k < NREL; k++) s += DAD[i * NREL + k] * RC[k * DIM + j];
    g_relT[idx] = s;
}

__global__ void rel_gemm2(const float* __restrict__ W) {
    int idx = blockIdx.x * blockDim.x + threadIdx.x;
    if (idx >= NREL * DIM) return;
    int i = idx >> 7, j = idx & 127;
    float s = 0.0f;
    for (int k = 0; k < DIM; k++) s += g_relT[i * DIM + k] * W[k * DIM + j];
    g_relC[idx] = s > 0.0f ? s : 0.0f;
}

// ---------------- gated output gather (float4/thread) ------------------------
__global__ void out_kernel(const int* __restrict__ samples,
                           const float* __restrict__ ent_emb,
                           const float* __restrict__ rel_emb,
                           const float* __restrict__ gate_e,
                           const float* __restrict__ gate_r,
                           float* __restrict__ out) {
    int idx = blockIdx.x * blockDim.x + threadIdx.x;  // S_SAMP*32
    if (idx >= S_SAMP * 32) return;
    int s = idx >> 5, q = idx & 31;
    float4 gev = ((const float4*)gate_e)[q];
    float4 grv = ((const float4*)gate_r)[q];
    float4 ge = make_float4(sigmoidf(gev.x), sigmoidf(gev.y), sigmoidf(gev.z), sigmoidf(gev.w));
    float4 gr = make_float4(sigmoidf(grv.x), sigmoidf(grv.y), sigmoidf(grv.z), sigmoidf(grv.w));
    int h = samples[s * 3 + 0];
    int r = samples[s * 3 + 1];
    int t = samples[s * 3 + 2];

    float4 a, b, o;
    a = ((const float4*)(ent_emb + (size_t)h * DIM))[q];
    b = ((const float4*)(g_XF + (size_t)h * DIM))[q];
    o.x = ge.x * a.x + (1.0f - ge.x) * b.x;
    o.y = ge.y * a.y + (1.0f - ge.y) * b.y;
    o.z = ge.z * a.z + (1.0f - ge.z) * b.z;
    o.w = ge.w * a.w + (1.0f - ge.w) * b.w;
    ((float4*)out)[idx] = o;

    a = ((const float4*)(rel_emb + (size_t)r * DIM))[q];
    b = ((const float4*)(g_relC + (size_t)r * DIM))[q];
    o.x = gr.x * a.x + (1.0f - gr.x) * b.x;
    o.y = gr.y * a.y + (1.0f - gr.y) * b.y;
    o.z = gr.z * a.z + (1.0f - gr.z) * b.z;
    o.w = gr.w * a.w + (1.0f - gr.w) * b.w;
    ((float4*)out)[S_SAMP * 32 + idx] = o;

    a = ((const float4*)(ent_emb + (size_t)t * DIM))[q];
    b = ((const float4*)(g_XF + (size_t)t * DIM))[q];
    o.x = ge.x * a.x + (1.0f - ge.x) * b.x;
    o.y = ge.y * a.y + (1.0f - ge.y) * b.y;
    o.z = ge.z * a.z + (1.0f - ge.z) * b.z;
    o.w = ge.w * a.w + (1.0f - ge.w) * b.w;
    ((float4*)out)[2 * S_SAMP * 32 + idx] = o;
}

// ---------------- launch -----------------------------------------------------
extern "C" void kernel_launch(void* const* d_in, const int* in_sizes, int n_in,
                              void* d_out, int out_size) {
    const int*   entity  = (const int*)d_in[0];
    const int*   eidx    = (const int*)d_in[1];
    const int*   etype   = (const int*)d_in[2];
    const float* enorm   = (const float*)d_in[3];
    const int*   samples = (const int*)d_in[4];
    const float* DAD     = (const float*)d_in[5];
    const float* ent_emb = (const float*)d_in[6];
    const float* rel_emb = (const float*)d_in[7];
    const float* ectx    = (const float*)d_in[8];
    const float* rctx    = (const float*)d_in[9];
    const float* rgw     = (const float*)d_in[10];
    const float* gate_e  = (const float*)d_in[11];
    const float* gate_r  = (const float*)d_in[12];
    const float* basis1  = (const float*)d_in[13];
    const float* att1    = (const float*)d_in[14];
    const float* root1   = (const float*)d_in[15];
    const float* bias1   = (const float*)d_in[16];
    const float* basis2  = (const float*)d_in[17];
    const float* att2    = (const float*)d_in[18];
    const float* root2   = (const float*)d_in[19];
    const float* bias2   = (const float*)d_in[20];
    float* out = (float*)d_out;

    const int* src = eidx;
    const int* dst = eidx + E_EDGES;

    static bool init_done = false;
    static cudaStream_t s1;
    static cudaEvent_t evRoot, evX0, evW1, evW2, evRel;
    if (!init_done) {
        cudaFuncSetAttribute(gemm_mma, cudaFuncAttributeMaxDynamicSharedMemorySize, SMEM_SZ);
        cudaStreamCreateWithFlags(&s1, cudaStreamNonBlocking);
        cudaEventCreateWithFlags(&evRoot, cudaEventDisableTiming);
        cudaEventCreateWithFlags(&evX0,   cudaEventDisableTiming);
        cudaEventCreateWithFlags(&evW1,   cudaEventDisableTiming);
        cudaEventCreateWithFlags(&evW2,   cudaEventDisableTiming);
        cudaEventCreateWithFlags(&evRel,  cudaEventDisableTiming);
        init_done = true;
    }

    const int TB = 256;

    // fork side stream off the (capture) default stream
    cudaEventRecord(evRoot, 0);
    cudaStreamWaitEvent(s1, evRoot, 0);

    // ---- main stream: slot table (payload-packed) ----
    zero_deg_k<<<(N_ENT + TB - 1) / TB, TB>>>();
    fill_k<<<(E_EDGES + TB - 1) / TB, TB>>>(dst, src, etype, enorm);

    // ---- side stream: gather_x0, W splits, relation GCN ----
    gather_x0<<<(N_ENT * 32 + TB - 1) / TB, TB, 0, s1>>>(entity, ectx);
    cudaEventRecord(evX0, s1);
    build_w_split<<<(DIM * KTOT + TB - 1) / TB, TB, 0, s1>>>(basis1, root1, 0);
    cudaEventRecord(evW1, s1);
    build_w_split<<<(DIM * KTOT + TB - 1) / TB, TB, 0, s1>>>(basis2, root2, 1);
    cudaEventRecord(evW2, s1);
    rel_gemm1<<<(NREL * DIM + TB - 1) / TB, TB, 0, s1>>>(DAD, rctx);
    rel_gemm2<<<(NREL * DIM + TB - 1) / TB, TB, 0, s1>>>(rgw);
    cudaEventRecord(evRel, s1);

    // ---- layer 1 (main stream) ----
    cudaStreamWaitEvent(0, evX0, 0);
    edge_gather<<<(N_ENT * 32 + TB - 1) / TB, TB>>>(att1);
    cudaStreamWaitEvent(0, evW1, 0);
    gemm_mma<<<PGRID, TB, SMEM_SZ>>>(bias1, 1, 0, N_ENT);

    // ---- layer 2 ----
    edge_gather<<<(N_ENT * 32 + TB - 1) / TB, TB>>>(att2);
    cudaStreamWaitEvent(0, evW2, 0);
    gemm_mma<<<PGRID, TB, SMEM_SZ>>>(bias2, 0, 1, N_ENT);

    // ---- gated gather ----
    cudaStreamWaitEvent(0, evRel, 0);
    out_kernel<<<(S_SAMP * 32 + TB - 1) / TB, TB>>>(samples, ent_emb, rel_emb,
                                                    gate_e, gate_r, out);
}

// round 16
// speedup vs baseline: 1.6205x; 1.6205x over previous
#include <cuda_runtime.h>
#include <cuda_bf16.h>
#include <math.h>
#include <stdint.h>

#define N_ENT   50000
#define NREL    200
#define DIM     128
#define NB      4
#define E_EDGES 200000
#define S_SAMP  20000
#define KTOT    640   /* GEMM K: 512 (Z) + 128 (X) */
#define MTILES  391   /* ceil(50000/128) */
#define CAP     128   /* slot capacity per dst */
#define CH      40    /* smem chunk row stride (halfs): 32 + pad */

// ---------------- scratch (device globals; no runtime allocation) ----------
__device__ __nv_bfloat16 g_Ab[(size_t)N_ENT * KTOT];  // A hi = [Zmean | X]
__device__ __nv_bfloat16 g_As[(size_t)N_ENT * KTOT];  // A lo
__device__ __nv_bfloat16 g_Wb[2][DIM * KTOT];         // W^T hi, per layer
__device__ __nv_bfloat16 g_Ws[2][DIM * KTOT];         // W^T lo, per layer
__device__ float g_XF[(size_t)N_ENT * DIM];           // current x (fp32)
__device__ int   g_deg[N_ENT];
__device__ int   g_ssrc[(size_t)N_ENT * CAP];         // slot payload: src node
__device__ int2  g_mt[(size_t)N_ENT * CAP];           // slot payload: (etype, norm)
__device__ float g_relT[NREL * DIM];
__device__ float g_relC[NREL * DIM];

// ---------------- PTX helpers ------------------------------------------------
__device__ __forceinline__ uint32_t smem_u32(const void* p) {
    uint32_t a;
    asm("{ .reg .u64 t; cvta.to.shared.u64 t, %1; cvt.u32.u64 %0, t; }"
        : "=r"(a) : "l"(p));
    return a;
}
__device__ __forceinline__ void cp16(uint32_t dst_s, const void* src) {
    asm volatile("cp.async.cg.shared.global [%0], [%1], 16;"
                 :: "r"(dst_s), "l"(src));
}
#define CP_COMMIT() asm volatile("cp.async.commit_group;" ::: "memory")
#define CP_WAIT1()  asm volatile("cp.async.wait_group 1;" ::: "memory")
#define CP_WAIT0()  asm volatile("cp.async.wait_group 0;" ::: "memory")

__device__ __forceinline__ void mma_bf16(float* d, const uint32_t* a,
                                         uint32_t b0, uint32_t b1) {
    asm volatile(
        "mma.sync.aligned.m16n8k16.row.col.f32.bf16.bf16.f32 "
        "{%0,%1,%2,%3}, {%4,%5,%6,%7}, {%8,%9}, {%0,%1,%2,%3};"
        : "+f"(d[0]), "+f"(d[1]), "+f"(d[2]), "+f"(d[3])
        : "r"(a[0]), "r"(a[1]), "r"(a[2]), "r"(a[3]), "r"(b0), "r"(b1));
}
#define LDSM4(r0, r1, r2, r3, addr) \
    asm volatile("ldmatrix.sync.aligned.m8n8.x4.shared.b16 {%0,%1,%2,%3}, [%4];" \
                 : "=r"(r0), "=r"(r1), "=r"(r2), "=r"(r3) : "r"(addr))

__device__ __forceinline__ uint32_t pack_bf2(float lo, float hi) {
    __nv_bfloat16 a = __float2bfloat16_rn(lo);
    __nv_bfloat16 b = __float2bfloat16_rn(hi);
    return (uint32_t)__bfloat16_as_ushort(a) |
           ((uint32_t)__bfloat16_as_ushort(b) << 16);
}
__device__ __forceinline__ void split2(float v, float& hi, float& lo) {
    __nv_bfloat16 h = __float2bfloat16_rn(v);
    hi = __bfloat162float(h);
    lo = v - hi;
}
__device__ __forceinline__ float sigmoidf(float x) {
    return 1.0f / (1.0f + expf(-x));
}

// ---------------- setup kernels ----------------------------------------------
__global__ void zero_deg_k() {
    int i = blockIdx.x * blockDim.x + threadIdx.x;
    if (i < N_ENT) g_deg[i] = 0;
}

// pack full edge payload into slot tables (one indirection level removed)
__global__ void fill_k(const int* __restrict__ dst, const int* __restrict__ src,
                       const int* __restrict__ etype, const float* __restrict__ enorm) {
    int e = blockIdx.x * blockDim.x + threadIdx.x;
    if (e >= E_EDGES) return;
    int d = dst[e];
    int pos = atomicAdd(&g_deg[d], 1);
    if (pos < CAP) {
        size_t off = (size_t)d * CAP + pos;
        g_ssrc[off] = src[e];
        g_mt[off] = make_int2(etype[e], __float_as_int(enorm[e]));
    }
}

// W^T[j][c]: c<512 -> basis[b=c/128][i=c%128][j] ; c>=512 -> root[c-512][j]
__global__ void build_w_split(const float* __restrict__ basis,
                              const float* __restrict__ root, int layer) {
    int idx = blockIdx.x * blockDim.x + threadIdx.x;  // DIM*KTOT
    if (idx >= DIM * KTOT) return;
    int j = idx / KTOT, c = idx % KTOT;
    float w;
    if (c < 512) w = basis[(size_t)c * DIM + j];
    else         w = root[(size_t)(c - 512) * DIM + j];
    float hi, lo;
    split2(w, hi, lo);
    g_Wb[layer][idx] = __float2bfloat16_rn(hi);
    g_Ws[layer][idx] = __float2bfloat16_rn(lo);
}

// X0 = entity_context_tab[entity] -> XF fp32 + bf16 splits (A cols 512..639)
__global__ void gather_x0(const int* __restrict__ entity,
                          const float* __restrict__ ectx) {
    int idx = blockIdx.x * blockDim.x + threadIdx.x;  // N_ENT*32
    if (idx >= N_ENT * 32) return;
    int n = idx >> 5, q = idx & 31;
    float4 x = ((const float4*)(ectx + (size_t)entity[n] * DIM))[q];
    ((float4*)(g_XF + (size_t)n * DIM))[q] = x;
    float h0, l0, h1, l1, h2, l2, h3, l3;
    split2(x.x, h0, l0); split2(x.y, h1, l1);
    split2(x.z, h2, l2); split2(x.w, h3, l3);
    size_t off = (size_t)n * KTOT + 512 + q * 4;
    *(uint2*)(g_Ab + off) = make_uint2(pack_bf2(h0, h1), pack_bf2(h2, h3));
    *(uint2*)(g_As + off) = make_uint2(pack_bf2(l0, l1), pack_bf2(l2, l3));
}

// ---------------- edge gather -------------------------------------------------
__device__ __forceinline__ void accum16(float* z, float4 a, float nrm, float4 x) {
    float c;
    c = a.x * nrm; z[0]  += c * x.x; z[1]  += c * x.y; z[2]  += c * x.z; z[3]  += c * x.w;
    c = a.y * nrm; z[4]  += c * x.x; z[5]  += c * x.y; z[6]  += c * x.z; z[7]  += c * x.w;
    c = a.z * nrm; z[8]  += c * x.x; z[9]  += c * x.y; z[10] += c * x.z; z[11] += c * x.w;
    c = a.w * nrm; z[12] += c * x.x; z[13] += c * x.y; z[14] += c * x.z; z[15] += c * x.w;
}

// warp per dst; 2-edge unroll, register-capped for occupancy
__global__ void __launch_bounds__(256, 5)
edge_gather(const float* __restrict__ att) {
    int d = (blockIdx.x * blockDim.x + threadIdx.x) >> 5;
    int lane = threadIdx.x & 31;
    if (d >= N_ENT) return;
    int degf = g_deg[d];
    int deg = degf < CAP ? degf : CAP;
    const int* ssrc = g_ssrc + (size_t)d * CAP;
    const int2* mt = g_mt + (size_t)d * CAP;

    float z[16];
#pragma unroll
    for (int i = 0; i < 16; i++) z[i] = 0.0f;

    int i = 0;
    for (; i + 2 <= deg; i += 2) {
        int s0 = ssrc[i], s1 = ssrc[i + 1];
        int4 m01 = *(const int4*)(mt + i);          // (et0,n0,et1,n1)
        float4 a0 = *(const float4*)(att + (size_t)m01.x * 4);
        float4 a1 = *(const float4*)(att + (size_t)m01.z * 4);
        float4 x0 = ((const float4*)(g_XF + (size_t)s0 * DIM))[lane];
        float4 x1 = ((const float4*)(g_XF + (size_t)s1 * DIM))[lane];
        accum16(z, a0, __int_as_float(m01.y), x0);
        accum16(z, a1, __int_as_float(m01.w), x1);
    }
    if (i < deg) {
        int s = ssrc[i];
        int2 m = mt[i];
        float4 a = *(const float4*)(att + (size_t)m.x * 4);
        float4 x = ((const float4*)(g_XF + (size_t)s * DIM))[lane];
        accum16(z, a, __int_as_float(m.y), x);
    }

    float inv = 1.0f / (float)(degf > 1 ? degf : 1);
#pragma unroll
    for (int b = 0; b < 4; b++) {
        float h0, l0, h1, l1, h2, l2, h3, l3;
        split2(z[b * 4 + 0] * inv, h0, l0);
        split2(z[b * 4 + 1] * inv, h1, l1);
        split2(z[b * 4 + 2] * inv, h2, l2);
        split2(z[b * 4 + 3] * inv, h3, l3);
        size_t off = (size_t)d * KTOT + b * 128 + lane * 4;
        *(uint2*)(g_Ab + off) = make_uint2(pack_bf2(h0, h1), pack_bf2(h2, h3));
        *(uint2*)(g_As + off) = make_uint2(pack_bf2(l0, l1), pack_bf2(l2, l3));
    }
}

// ---------------- 3xBF16 GEMM: out[M,128] = relu(A[M,640] @ W^T + bias) ------
#define BUF_HALFS (2 * 128 * CH)      /* 10240 halfs = 20480 B per buffer */
#define SMEM_SZ   (4 * BUF_HALFS * 2) /* A(2) + W(2) = 81920 B */

__device__ __forceinline__ void load_chunk(uint32_t sbase, const __nv_bfloat16* hi,
                                           const __nv_bfloat16* lo, int row0,
                                           int maxrow, int kc, int tid) {
    int r = tid >> 1, h = tid & 1;
    int gr = row0 + r;
    if (gr >= maxrow) gr = 0;
    const __nv_bfloat16* ph = hi + (size_t)gr * KTOT + kc * 32 + h * 16;
    const __nv_bfloat16* pl = lo + (size_t)gr * KTOT + kc * 32 + h * 16;
    uint32_t dh = sbase + (uint32_t)(r * CH + h * 16) * 2;
    uint32_t dl = dh + (uint32_t)(128 * CH) * 2;
    cp16(dh, ph);       cp16(dh + 16, ph + 8);
    cp16(dl, pl);       cp16(dl + 16, pl + 8);
}

__global__ void __launch_bounds__(256, 2)
gemm_mma(const float* __restrict__ bias, int write_split, int layer, int M) {
    extern __shared__ char smraw[];
    uint32_t sA_u = smem_u32(smraw);
    uint32_t sW_u = sA_u + 2 * BUF_HALFS * 2;
    const __nv_bfloat16* Wb = g_Wb[layer];
    const __nv_bfloat16* Ws = g_Ws[layer];

    int tid = threadIdx.x;
    int wid = tid >> 5;
    int lane = tid & 31;
    int wm = (wid & 3) * 32;
    int wn = (wid >> 2) * 64;
    int f_r = lane & 15;
    int f_c = (lane >> 4) << 3;
    int m0 = blockIdx.x * 128;

    float acc[2][8][4];
#pragma unroll
    for (int i = 0; i < 2; i++)
#pragma unroll
        for (int j = 0; j < 8; j++)
#pragma unroll
            for (int q = 0; q < 4; q++) acc[i][j][q] = 0.0f;

    load_chunk(sA_u, g_Ab, g_As, m0, M, 0, tid);
    load_chunk(sW_u, Wb, Ws, 0, 128, 0, tid);
    CP_COMMIT();

    int buf = 0;
    for (int kc = 0; kc < 20; kc++) {
        if (kc + 1 < 20) {
            uint32_t nb = (uint32_t)((buf ^ 1) * BUF_HALFS) * 2;
            load_chunk(sA_u + nb, g_Ab, g_As, m0, M, kc + 1, tid);
            load_chunk(sW_u + nb, Wb, Ws, 0, 128, kc + 1, tid);
            CP_COMMIT();
            CP_WAIT1();
        } else {
            CP_WAIT0();
        }
        __syncthreads();

        uint32_t sa = sA_u + (uint32_t)(buf * BUF_HALFS) * 2;
        uint32_t sw = sW_u + (uint32_t)(buf * BUF_HALFS) * 2;
#pragma unroll
        for (int k16 = 0; k16 < 2; k16++) {
            int ak = k16 * 16 + f_c;
            uint32_t ab[2][4], av[2][4];
#pragma unroll
            for (int ma = 0; ma < 2; ma++) {
                uint32_t ad = sa + (uint32_t)((wm + ma * 16 + f_r) * CH + ak) * 2;
                LDSM4(ab[ma][0], ab[ma][1], ab[ma][2], ab[ma][3], ad);
                ad += (uint32_t)(128 * CH) * 2;
                LDSM4(av[ma][0], av[ma][1], av[ma][2], av[ma][3], ad);
            }
            uint32_t wb[4][4], ws[4][4];
#pragma unroll
            for (int g = 0; g < 4; g++) {
                uint32_t off = (uint32_t)((wn + g * 16 + f_r) * CH + ak) * 2;
                LDSM4(wb[g][0], wb[g][1], wb[g][2], wb[g][3], sw + off);
                LDSM4(ws[g][0], ws[g][1], ws[g][2], ws[g][3],
                      sw + (uint32_t)(128 * CH) * 2 + off);
            }
#pragma unroll
            for (int ma = 0; ma < 2; ma++)
#pragma unroll
                for (int g = 0; g < 4; g++)
#pragma unroll
                    for (int oc = 0; oc < 2; oc++) {
                        int na = g * 2 + oc;
                        mma_bf16(acc[ma][na], ab[ma], wb[g][oc], wb[g][oc + 2]);
                        mma_bf16(acc[ma][na], ab[ma], ws[g][oc], ws[g][oc + 2]);
                        mma_bf16(acc[ma][na], av[ma], wb[g][oc], wb[g][oc + 2]);
                    }
        }
        __syncthreads();
        buf ^= 1;
    }

    // ---- epilogue: +bias, relu -> XF fp32 (+ bf16 splits for next layer) ----
    int lr = lane >> 2, lc = lane & 3;
#pragma unroll
    for (int ma = 0; ma < 2; ma++) {
#pragma unroll
        for (int rr = 0; rr < 2; rr++) {
            int gr = m0 + wm + ma * 16 + rr * 8 + lr;
            if (gr >= M) continue;
#pragma unroll
            for (int na = 0; na < 8; na++) {
                int gc = wn + na * 8 + lc * 2;
                float v0 = acc[ma][na][rr * 2 + 0] + bias[gc];
                float v1 = acc[ma][na][rr * 2 + 1] + bias[gc + 1];
                v0 = v0 > 0.0f ? v0 : 0.0f;
                v1 = v1 > 0.0f ? v1 : 0.0f;
                *(float2*)(g_XF + (size_t)gr * DIM + gc) = make_float2(v0, v1);
                if (write_split) {
                    float h0, l0, h1, l1;
                    split2(v0, h0, l0);
                    split2(v1, h1, l1);
                    size_t off = (size_t)gr * KTOT + 512 + gc;
                    *(uint32_t*)(g_Ab + off) = pack_bf2(h0, h1);
                    *(uint32_t*)(g_As + off) = pack_bf2(l0, l1);
                }
            }
        }
    }
}

// ---------------- relation GCN (tiny) ----------------------------------------
__global__ void rel_gemm1(const float* __restrict__ DAD, const float* __restrict__ RC) {
    int idx = blockIdx.x * blockDim.x + threadIdx.x;
    if (idx >= NREL * DIM) return;
    int i = idx >> 7, j = idx & 127;
    float s = 0.0f;
    for (int k = 0; k < NREL; k++) s += DAD[i * NREL + k] * RC[k * DIM + j];
    g_relT[idx] = s;
}

__global__ void rel_gemm2(const float* __restrict__ W) {
    int idx = blockIdx.x * blockDim.x + threadIdx.x;
    if (idx >= NREL * DIM) return;
    int i = idx >> 7, j = idx & 127;
    float s = 0.0f;
    for (int k = 0; k < DIM; k++) s += g_relT[i * DIM + k] * W[k * DIM + j];
    g_relC[idx] = s > 0.0f ? s : 0.0f;
}

// ---------------- gated output gather (float4/thread) ------------------------
__global__ void out_kernel(const int* __restrict__ samples,
                           const float* __restrict__ ent_emb,
                           const float* __restrict__ rel_emb,
                           const float* __restrict__ gate_e,
                           const float* __restrict__ gate_r,
                           float* __restrict__ out) {
    int idx = blockIdx.x * blockDim.x + threadIdx.x;  // S_SAMP*32
    if (idx >= S_SAMP * 32) return;
    int s = idx >> 5, q = idx & 31;
    float4 gev = ((const float4*)gate_e)[q];
    float4 grv = ((const float4*)gate_r)[q];
    float4 ge = make_float4(sigmoidf(gev.x), sigmoidf(gev.y), sigmoidf(gev.z), sigmoidf(gev.w));
    float4 gr = make_float4(sigmoidf(grv.x), sigmoidf(grv.y), sigmoidf(grv.z), sigmoidf(grv.w));
    int h = samples[s * 3 + 0];
    int r = samples[s * 3 + 1];
    int t = samples[s * 3 + 2];

    float4 a, b, o;
    a = ((const float4*)(ent_emb + (size_t)h * DIM))[q];
    b = ((const float4*)(g_XF + (size_t)h * DIM))[q];
    o.x = ge.x * a.x + (1.0f - ge.x) * b.x;
    o.y = ge.y * a.y + (1.0f - ge.y) * b.y;
    o.z = ge.z * a.z + (1.0f - ge.z) * b.z;
    o.w = ge.w * a.w + (1.0f - ge.w) * b.w;
    ((float4*)out)[idx] = o;

    a = ((const float4*)(rel_emb + (size_t)r * DIM))[q];
    b = ((const float4*)(g_relC + (size_t)r * DIM))[q];
    o.x = gr.x * a.x + (1.0f - gr.x) * b.x;
    o.y = gr.y * a.y + (1.0f - gr.y) * b.y;
    o.z = gr.z * a.z + (1.0f - gr.z) * b.z;
    o.w = gr.w * a.w + (1.0f - gr.w) * b.w;
    ((float4*)out)[S_SAMP * 32 + idx] = o;

    a = ((const float4*)(ent_emb + (size_t)t * DIM))[q];
    b = ((const float4*)(g_XF + (size_t)t * DIM))[q];
    o.x = ge.x * a.x + (1.0f - ge.x) * b.x;
    o.y = ge.y * a.y + (1.0f - ge.y) * b.y;
    o.z = ge.z * a.z + (1.0f - ge.z) * b.z;
    o.w = ge.w * a.w + (1.0f - ge.w) * b.w;
    ((float4*)out)[2 * S_SAMP * 32 + idx] = o;
}

// ---------------- launch -----------------------------------------------------
extern "C" void kernel_launch(void* const* d_in, const int* in_sizes, int n_in,
                              void* d_out, int out_size) {
    const int*   entity  = (const int*)d_in[0];
    const int*   eidx    = (const int*)d_in[1];
    const int*   etype   = (const int*)d_in[2];
    const float* enorm   = (const float*)d_in[3];
    const int*   samples = (const int*)d_in[4];
    const float* DAD     = (const float*)d_in[5];
    const float* ent_emb = (const float*)d_in[6];
    const float* rel_emb = (const float*)d_in[7];
    const float* ectx    = (const float*)d_in[8];
    const float* rctx    = (const float*)d_in[9];
    const float* rgw     = (const float*)d_in[10];
    const float* gate_e  = (const float*)d_in[11];
    const float* gate_r  = (const float*)d_in[12];
    const float* basis1  = (const float*)d_in[13];
    const float* att1    = (const float*)d_in[14];
    const float* root1   = (const float*)d_in[15];
    const float* bias1   = (const float*)d_in[16];
    const float* basis2  = (const float*)d_in[17];
    const float* att2    = (const float*)d_in[18];
    const float* root2   = (const float*)d_in[19];
    const float* bias2   = (const float*)d_in[20];
    float* out = (float*)d_out;

    const int* src = eidx;
    const int* dst = eidx + E_EDGES;

    static bool init_done = false;
    static cudaStream_t s1;
    static cudaEvent_t evRoot, evX0, evW1, evW2, evRel;
    if (!init_done) {
        cudaFuncSetAttribute(gemm_mma, cudaFuncAttributeMaxDynamicSharedMemorySize, SMEM_SZ);
        cudaStreamCreateWithFlags(&s1, cudaStreamNonBlocking);
        cudaEventCreateWithFlags(&evRoot, cudaEventDisableTiming);
        cudaEventCreateWithFlags(&evX0,   cudaEventDisableTiming);
        cudaEventCreateWithFlags(&evW1,   cudaEventDisableTiming);
        cudaEventCreateWithFlags(&evW2,   cudaEventDisableTiming);
        cudaEventCreateWithFlags(&evRel,  cudaEventDisableTiming);
        init_done = true;
    }

    const int TB = 256;

    // fork side stream off the (capture) default stream
    cudaEventRecord(evRoot, 0);
    cudaStreamWaitEvent(s1, evRoot, 0);

    // ---- main stream: slot table (payload-packed) ----
    zero_deg_k<<<(N_ENT + TB - 1) / TB, TB>>>();
    fill_k<<<(E_EDGES + TB - 1) / TB, TB>>>(dst, src, etype, enorm);

    // ---- side stream: gather_x0, W splits, relation GCN ----
    gather_x0<<<(N_ENT * 32 + TB - 1) / TB, TB, 0, s1>>>(entity, ectx);
    cudaEventRecord(evX0, s1);
    build_w_split<<<(DIM * KTOT + TB - 1) / TB, TB, 0, s1>>>(basis1, root1, 0);
    cudaEventRecord(evW1, s1);
    build_w_split<<<(DIM * KTOT + TB - 1) / TB, TB, 0, s1>>>(basis2, root2, 1);
    cudaEventRecord(evW2, s1);
    rel_gemm1<<<(NREL * DIM + TB - 1) / TB, TB, 0, s1>>>(DAD, rctx);
    rel_gemm2<<<(NREL * DIM + TB - 1) / TB, TB, 0, s1>>>(rgw);
    cudaEventRecord(evRel, s1);

    // ---- layer 1 (main stream) ----
    cudaStreamWaitEvent(0, evX0, 0);
    edge_gather<<<(N_ENT * 32 + TB - 1) / TB, TB>>>(att1);
    cudaStreamWaitEvent(0, evW1, 0);
    gemm_mma<<<MTILES, TB, SMEM_SZ>>>(bias1, 1, 0, N_ENT);

    // ---- layer 2 ----
    edge_gather<<<(N_ENT * 32 + TB - 1) / TB, TB>>>(att2);
    cudaStreamWaitEvent(0, evW2, 0);
    gemm_mma<<<MTILES, TB, SMEM_SZ>>>(bias2, 0, 1, N_ENT);

    // ---- gated gather ----
    cudaStreamWaitEvent(0, evRel, 0);
    out_kernel<<<(S_SAMP * 32 + TB - 1) / TB, TB>>>(samples, ent_emb, rel_emb,
                                                    gate_e, gate_r, out);
}